// round 16
// baseline (speedup 1.0000x reference)
#include <cuda_runtime.h>
#include <cuda_fp16.h>
#include <cstdint>

#define NROWS 100000
#define NPAD  100096          // 782 * 128
#define DIM 256
#define EPS 1e-6f
#define KV_SCALE_INV 256.0f   // KVh = KV / 256

#define SA 40                 // A-tile row stride (halves), 128 rows x 32 k
#define SB 136                // B/K/V-tile row stride (halves), 32 rows x 128 cols
#define ABYTES (128 * SA * 2)
#define BBYTES (32 * SB * 2)
#define STAGES 4              // qkv/out: 4 stages, ONE barrier/tile (R15 best)
#define KV_STAGES 3           // kv: 3 stages, two barriers (R10 best)

#define QKV_SMEM (STAGES * (ABYTES + BBYTES))      // 75776
#define OUT_SMEM (STAGES * (ABYTES + BBYTES))
#define KV_SMEM  (KV_STAGES * 2 * BBYTES)          // 52224

#define KV_BLOCKS 500         // 125 chunks x 4 tile positions
#define KV_TILES 25           // 25*32 = 800 rows/chunk; 125*800 = 100000 exactly
#define NORM_BLOCKS 296

// Scratch (allocation-guard-safe __device__ globals)
__device__ __half g_xh[NPAD * DIM];      // x as fp16 (pad rows stay zero)
__device__ __half g_Q[NPAD * DIM];
__device__ __half g_K[NPAD * DIM];
__device__ __half g_V[NPAD * DIM];
__device__ __half g_Wh[3 * DIM * DIM];   // [z][k][n] fp16
__device__ float  g_KV[DIM * DIM];
__device__ __half g_KVh[DIM * DIM];      // KV / 256 as fp16, [d][e]
__device__ float  g_ksum[DIM];
__device__ float  g_norm[NROWS];

// ---------------------------------------------------------------------------
// PTX helpers
// ---------------------------------------------------------------------------
__device__ __forceinline__ uint32_t smem_u32(const void* p) {
    uint32_t a;
    asm("{ .reg .u64 t; cvta.to.shared.u64 t, %1; cvt.u32.u64 %0, t; }" : "=r"(a) : "l"(p));
    return a;
}

__device__ __forceinline__ void cp16(uint32_t dst, const void* src) {
    asm volatile("cp.async.cg.shared.global [%0], [%1], 16;" :: "r"(dst), "l"(src));
}
#define CP_COMMIT() asm volatile("cp.async.commit_group;" ::: "memory")
#define CP_WAIT(n)  asm volatile("cp.async.wait_group %0;" :: "n"(n) : "memory")

#define LDSM_X4(r, addr) \
    asm volatile("ldmatrix.sync.aligned.m8n8.x4.shared.b16 {%0,%1,%2,%3}, [%4];" \
                 : "=r"((r)[0]), "=r"((r)[1]), "=r"((r)[2]), "=r"((r)[3]) : "r"(addr))
#define LDSM_X4T(r, addr) \
    asm volatile("ldmatrix.sync.aligned.m8n8.x4.trans.shared.b16 {%0,%1,%2,%3}, [%4];" \
                 : "=r"((r)[0]), "=r"((r)[1]), "=r"((r)[2]), "=r"((r)[3]) : "r"(addr))

__device__ __forceinline__ void mma_fp16(float c[4], const uint32_t a[4],
                                         uint32_t b0, uint32_t b1) {
    asm volatile(
        "mma.sync.aligned.m16n8k16.row.col.f32.f16.f16.f32 "
        "{%0,%1,%2,%3},{%4,%5,%6,%7},{%8,%9},{%0,%1,%2,%3};\n"
        : "+f"(c[0]), "+f"(c[1]), "+f"(c[2]), "+f"(c[3])
        : "r"(a[0]), "r"(a[1]), "r"(a[2]), "r"(a[3]), "r"(b0), "r"(b1));
}

__device__ __forceinline__ uint32_t pack_h2(float a, float b) {
    __half2 h = __floats2half2_rn(a, b);
    return *reinterpret_cast<uint32_t*>(&h);
}

// ---------------------------------------------------------------------------
// prep: x -> fp16, W -> fp16, AND zero KV/ksum accumulators (init fused)
// grid 12661 x 256 threads
// ---------------------------------------------------------------------------
__global__ void prep_kernel(const float* __restrict__ x,
                            const float* __restrict__ Wq,
                            const float* __restrict__ Wk,
                            const float* __restrict__ Wv) {
    const long id = (long)blockIdx.x * 256 + threadIdx.x;
    const long xgroups = (long)NROWS * DIM / 8;     // 3,200,000
    const long wgroups = 3 * DIM * DIM / 8;         // 24,576
    if (id < xgroups + wgroups) {
        const float* src;
        __half* dst;
        long off;
        if (id < xgroups) {
            src = x; dst = g_xh; off = id * 8;
        } else {
            const long wi = id - xgroups;
            const int z = (int)(wi >> 13);           // 8192 groups per matrix
            src = (z == 0) ? Wq : (z == 1) ? Wk : Wv;
            dst = g_Wh + z * DIM * DIM;
            off = (wi & 8191) * 8;
        }
        const float4 f0 = *(const float4*)&src[off];
        const float4 f1 = *(const float4*)&src[off + 4];
        uint4 u;
        u.x = pack_h2(f0.x, f0.y); u.y = pack_h2(f0.z, f0.w);
        u.z = pack_h2(f1.x, f1.y); u.w = pack_h2(f1.z, f1.w);
        *(uint4*)&dst[off] = u;
    } else {
        const long id3 = id - (xgroups + wgroups);   // 0..16639 used
        if (id3 < DIM * DIM / 4) {                   // 16384: zero KV (float4)
            *(float4*)&g_KV[id3 * 4] = make_float4(0.f, 0.f, 0.f, 0.f);
            if (id3 < DIM / 4)                       // 64: zero ksum
                *(float4*)&g_ksum[id3 * 4] = make_float4(0.f, 0.f, 0.f, 0.f);
        }
    }
}

// ---------------------------------------------------------------------------
// qkv: 256 thr, 128x128 tile, 4x2 warps of 32x64. ksum fused (z==1)
// grid (6, 782). 4-stage single-barrier pipeline.  (R15 best shape)
// ---------------------------------------------------------------------------
__global__ __launch_bounds__(256, 2) void qkv_kernel(
    const float* __restrict__ bq, const float* __restrict__ bk,
    const float* __restrict__ bv)
{
    extern __shared__ char dsm[];
    __shared__ float colsum[128];

    const int t = threadIdx.x;
    const int l = t & 31, w = t >> 5;
    const int wm = w >> 1, wn = w & 1;

    const int zy = blockIdx.x;
    const int z = zy >> 1;
    const int col0 = (zy & 1) * 128;
    const int row0 = blockIdx.y * 128;

    const __half* Wh = g_Wh + z * DIM * DIM;
    const float* bias = (z == 0) ? bq : (z == 1) ? bk : bv;
    __half* C = (z == 0) ? g_Q : (z == 1) ? g_K : g_V;
    const bool relu = (z < 2);

    if (t < 128) colsum[t] = 0.0f;

    const uint32_t as_base = smem_u32(dsm);
    const uint32_t bs_base = as_base + STAGES * ABYTES;
    const int aoff = (l & 15) * SA + (l >> 4) * 8;
    const int boff = ((l & 7) + ((l >> 3) & 1) * 8) * SB + (l >> 4) * 8;

    float c[2][8][4];
#pragma unroll
    for (int mt = 0; mt < 2; mt++)
#pragma unroll
        for (int nt = 0; nt < 8; nt++)
#pragma unroll
            for (int r = 0; r < 4; r++) c[mt][nt][r] = 0.0f;

    auto cp = [&](int kt) {
        const int s = kt % STAGES;
        const uint32_t da = as_base + s * ABYTES;
#pragma unroll
        for (int i = 0; i < 2; i++) {
            const int id = t + i * 256;
            const int row = id >> 2, cg = id & 3;
            cp16(da + (row * SA + cg * 8) * 2,
                 &g_xh[(row0 + row) * DIM + kt * 32 + cg * 8]);
        }
        const uint32_t db = bs_base + s * BBYTES;
#pragma unroll
        for (int i = 0; i < 2; i++) {
            const int id = t + i * 256;
            const int row = id >> 4, cg = id & 15;
            cp16(db + (row * SB + cg * 8) * 2,
                 &Wh[(kt * 32 + row) * DIM + col0 + cg * 8]);
        }
        CP_COMMIT();
    };
    auto compute = [&](int s) {
        const uint32_t ab = as_base + s * ABYTES;
        const uint32_t bb = bs_base + s * BBYTES;
#pragma unroll
        for (int ks = 0; ks < 2; ks++) {
            uint32_t a[2][4];
#pragma unroll
            for (int mt = 0; mt < 2; mt++)
                LDSM_X4(a[mt], ab + 2 * ((wm * 32 + mt * 16) * SA + ks * 16 + aoff));
            uint32_t b[4][4];
#pragma unroll
            for (int nt2 = 0; nt2 < 4; nt2++)
                LDSM_X4T(b[nt2], bb + 2 * (ks * 16 * SB + wn * 64 + nt2 * 16 + boff));
#pragma unroll
            for (int mt = 0; mt < 2; mt++)
#pragma unroll
                for (int nt = 0; nt < 8; nt++) {
                    const int nt2 = nt >> 1, i0 = (nt & 1) * 2;
                    mma_fp16(c[mt][nt], a[mt], b[nt2][i0], b[nt2][i0 + 1]);
                }
        }
    };

    cp(0); cp(1);
#pragma unroll 1
    for (int kt = 0; kt < 8; kt++) {
        if (kt + 2 < 8) cp(kt + 2);
        if (kt < 6) CP_WAIT(2); else if (kt == 6) CP_WAIT(1); else CP_WAIT(0);
        __syncthreads();
        compute(kt % STAGES);
    }

#pragma unroll
    for (int mt = 0; mt < 2; mt++) {
        const int gr0 = row0 + wm * 32 + mt * 16 + (l >> 2);
        const int gr1 = gr0 + 8;
#pragma unroll
        for (int nt = 0; nt < 8; nt++) {
            const int col = col0 + wn * 64 + nt * 8 + (l & 3) * 2;
            const float bb0 = bias[col], bb1 = bias[col + 1];
            float v0 = c[mt][nt][0] + bb0, v1 = c[mt][nt][1] + bb1;
            float v2 = c[mt][nt][2] + bb0, v3 = c[mt][nt][3] + bb1;
            if (relu) {
                v0 = fmaxf(v0, 0.f); v1 = fmaxf(v1, 0.f);
                v2 = fmaxf(v2, 0.f); v3 = fmaxf(v3, 0.f);
            }
            *(__half2*)&C[gr0 * DIM + col] = __floats2half2_rn(v0, v1);
            *(__half2*)&C[gr1 * DIM + col] = __floats2half2_rn(v2, v3);
            if (z == 1) {
                float s0 = (gr0 < NROWS ? v0 : 0.f) + (gr1 < NROWS ? v2 : 0.f);
                float s1 = (gr0 < NROWS ? v1 : 0.f) + (gr1 < NROWS ? v3 : 0.f);
                atomicAdd(&colsum[col - col0], s0);
                atomicAdd(&colsum[col - col0 + 1], s1);
            }
        }
    }
    if (z == 1) {
        __syncthreads();
        if (t < 128) atomicAdd(&g_ksum[col0 + t], colsum[t]);
    }
}

// ---------------------------------------------------------------------------
// kv + norm combined launch. 128 threads.
//   blocks [0, 500):   kv split-k, R10 shape (3-stage, two barriers)
//   blocks [500, 796): norm: g_norm[n] = dot(Q[n], ksum) + EPS
// Norm blocks fill kv's idle DRAM capacity / tail wave.
// ---------------------------------------------------------------------------
__global__ __launch_bounds__(128, 2) void kvnorm_kernel() {
    extern __shared__ char dsm[];
    const int t = threadIdx.x;

    if (blockIdx.x >= KV_BLOCKS) {
        // ---- norm block ----
        float* ks = (float*)dsm;
        ks[t] = g_ksum[t];
        ks[t + 128] = g_ksum[t + 128];
        __syncthreads();

        const int lane = t & 31;
        const int gw = ((blockIdx.x - KV_BLOCKS) * 128 + t) >> 5;
        const int nw = (NORM_BLOCKS * 128) >> 5;
        for (int p = gw; p < NROWS / 2; p += nw) {
            const int r0 = p * 2, r1 = p * 2 + 1;
            const uint4 raw0 = *(const uint4*)&g_Q[r0 * DIM + lane * 8];
            const uint4 raw1 = *(const uint4*)&g_Q[r1 * DIM + lane * 8];
            const __half2* h0 = (const __half2*)&raw0;
            const __half2* h1 = (const __half2*)&raw1;
            float s0 = 0.0f, s1 = 0.0f;
#pragma unroll
            for (int i = 0; i < 4; i++) {
                const float k0 = ks[lane * 8 + i * 2], k1 = ks[lane * 8 + i * 2 + 1];
                float2 f0 = __half22float2(h0[i]);
                float2 f1 = __half22float2(h1[i]);
                s0 += f0.x * k0 + f0.y * k1;
                s1 += f1.x * k0 + f1.y * k1;
            }
#pragma unroll
            for (int o = 16; o; o >>= 1) {
                s0 += __shfl_xor_sync(0xffffffffu, s0, o);
                s1 += __shfl_xor_sync(0xffffffffu, s1, o);
            }
            if (lane == 0) { g_norm[r0] = s0 + EPS; g_norm[r1] = s1 + EPS; }
        }
        return;
    }

    // ---- kv block (R10 shape: 3-stage, two barriers, 64x64 warp tiles) ----
    const int l = t & 31, w = t >> 5;
    const int wm = w >> 1, wn = w & 1;

    const int bid = blockIdx.x;
    const int d0 = (bid & 1) * 128;
    const int e0 = ((bid >> 1) & 1) * 128;
    const int n0 = (bid >> 2) * (KV_TILES * 32);

    const uint32_t kb_base = smem_u32(dsm);
    const uint32_t vb_base = kb_base + KV_STAGES * BBYTES;
    const int kaoff = ((l & 7) + (l >> 4) * 8) * SB + ((l >> 3) & 1) * 8;
    const int boff  = ((l & 7) + ((l >> 3) & 1) * 8) * SB + (l >> 4) * 8;

    float c[4][8][4];
#pragma unroll
    for (int mt = 0; mt < 4; mt++)
#pragma unroll
        for (int nt = 0; nt < 8; nt++)
#pragma unroll
            for (int r = 0; r < 4; r++) c[mt][nt][r] = 0.0f;

    auto cp = [&](int kt) {
        const int s = kt % KV_STAGES;
        const uint32_t kd = kb_base + s * BBYTES;
        const uint32_t vd = vb_base + s * BBYTES;
        const int gn0 = n0 + kt * 32;
#pragma unroll
        for (int i = 0; i < 4; i++) {
            const int id = t + i * 128;
            const int row = id >> 4, cg = id & 15;
            cp16(kd + (row * SB + cg * 8) * 2, &g_K[(gn0 + row) * DIM + d0 + cg * 8]);
            cp16(vd + (row * SB + cg * 8) * 2, &g_V[(gn0 + row) * DIM + e0 + cg * 8]);
        }
        CP_COMMIT();
    };
    auto compute = [&](int s) {
        const uint32_t kb = kb_base + s * BBYTES;
        const uint32_t vb = vb_base + s * BBYTES;
#pragma unroll
        for (int ks = 0; ks < 2; ks++) {
            uint32_t a[4][4];
#pragma unroll
            for (int mt = 0; mt < 4; mt++)
                LDSM_X4T(a[mt], kb + 2 * (ks * 16 * SB + wm * 64 + mt * 16 + kaoff));
            uint32_t b[4][4];
#pragma unroll
            for (int nt2 = 0; nt2 < 4; nt2++)
                LDSM_X4T(b[nt2], vb + 2 * (ks * 16 * SB + wn * 64 + nt2 * 16 + boff));
#pragma unroll
            for (int mt = 0; mt < 4; mt++)
#pragma unroll
                for (int nt = 0; nt < 8; nt++) {
                    const int nt2 = nt >> 1, i0 = (nt & 1) * 2;
                    mma_fp16(c[mt][nt], a[mt], b[nt2][i0], b[nt2][i0 + 1]);
                }
        }
    };

    cp(0); cp(1);
#pragma unroll 1
    for (int kt = 0; kt < KV_TILES; kt++) {
        if (kt + 2 < KV_TILES) cp(kt + 2);
        if (kt < KV_TILES - 2) CP_WAIT(2);
        else if (kt == KV_TILES - 2) CP_WAIT(1);
        else CP_WAIT(0);
        __syncthreads();
        compute(kt % KV_STAGES);
        __syncthreads();
    }

#pragma unroll
    for (int mt = 0; mt < 4; mt++) {
        const int dr0 = d0 + wm * 64 + mt * 16 + (l >> 2);
#pragma unroll
        for (int nt = 0; nt < 8; nt++) {
            const int ec = e0 + wn * 64 + nt * 8 + (l & 3) * 2;
            atomicAdd(&g_KV[dr0 * DIM + ec],           c[mt][nt][0]);
            atomicAdd(&g_KV[dr0 * DIM + ec + 1],       c[mt][nt][1]);
            atomicAdd(&g_KV[(dr0 + 8) * DIM + ec],     c[mt][nt][2]);
            atomicAdd(&g_KV[(dr0 + 8) * DIM + ec + 1], c[mt][nt][3]);
        }
    }
}

// ---------------------------------------------------------------------------
// kvh: KVh = fp16(KV / 256)
// ---------------------------------------------------------------------------
__global__ void kvh_kernel() {
    const int i = (blockIdx.x * 256 + threadIdx.x) * 4;
    const float4 f = *(const float4*)&g_KV[i];
    const float s = 1.0f / KV_SCALE_INV;
    uint2 u;
    u.x = pack_h2(f.x * s, f.y * s);
    u.y = pack_h2(f.z * s, f.w * s);
    *(uint2*)&g_KVh[i] = u;
}

// ---------------------------------------------------------------------------
// out: out = (Q @ KVh) * 256 / norm.  R15 shape, 4-stage single-barrier.
// grid (2, 782)
// ---------------------------------------------------------------------------
__global__ __launch_bounds__(256, 2) void out_kernel(float* __restrict__ out) {
    extern __shared__ char dsm[];

    const int t = threadIdx.x;
    const int l = t & 31, w = t >> 5;
    const int wm = w >> 1, wn = w & 1;

    const int col0 = blockIdx.x * 128;
    const int row0 = blockIdx.y * 128;

    const uint32_t as_base = smem_u32(dsm);
    const uint32_t bs_base = as_base + STAGES * ABYTES;
    const int aoff = (l & 15) * SA + (l >> 4) * 8;
    const int boff = ((l & 7) + ((l >> 3) & 1) * 8) * SB + (l >> 4) * 8;

    float c[2][8][4];
#pragma unroll
    for (int mt = 0; mt < 2; mt++)
#pragma unroll
        for (int nt = 0; nt < 8; nt++)
#pragma unroll
            for (int r = 0; r < 4; r++) c[mt][nt][r] = 0.0f;

    auto cp = [&](int kt) {
        const int s = kt % STAGES;
        const uint32_t da = as_base + s * ABYTES;
#pragma unroll
        for (int i = 0; i < 2; i++) {
            const int id = t + i * 256;
            const int row = id >> 2, cg = id & 3;
            cp16(da + (row * SA + cg * 8) * 2,
                 &g_Q[(row0 + row) * DIM + kt * 32 + cg * 8]);
        }
        const uint32_t db = bs_base + s * BBYTES;
#pragma unroll
        for (int i = 0; i < 2; i++) {
            const int id = t + i * 256;
            const int row = id >> 4, cg = id & 15;
            cp16(db + (row * SB + cg * 8) * 2,
                 &g_KVh[(kt * 32 + row) * DIM + col0 + cg * 8]);
        }
        CP_COMMIT();
    };
    auto compute = [&](int s) {
        const uint32_t ab = as_base + s * ABYTES;
        const uint32_t bb = bs_base + s * BBYTES;
#pragma unroll
        for (int ks = 0; ks < 2; ks++) {
            uint32_t a[2][4];
#pragma unroll
            for (int mt = 0; mt < 2; mt++)
                LDSM_X4(a[mt], ab + 2 * ((wm * 32 + mt * 16) * SA + ks * 16 + aoff));
            uint32_t b[4][4];
#pragma unroll
            for (int nt2 = 0; nt2 < 4; nt2++)
                LDSM_X4T(b[nt2], bb + 2 * (ks * 16 * SB + wn * 64 + nt2 * 16 + boff));
#pragma unroll
            for (int mt = 0; mt < 2; mt++)
#pragma unroll
                for (int nt = 0; nt < 8; nt++) {
                    const int nt2 = nt >> 1, i0 = (nt & 1) * 2;
                    mma_fp16(c[mt][nt], a[mt], b[nt2][i0], b[nt2][i0 + 1]);
                }
        }
    };

    cp(0); cp(1);
#pragma unroll 1
    for (int kt = 0; kt < 8; kt++) {
        if (kt + 2 < 8) cp(kt + 2);
        if (kt < 6) CP_WAIT(2); else if (kt == 6) CP_WAIT(1); else CP_WAIT(0);
        __syncthreads();
        compute(kt % STAGES);
    }

#pragma unroll
    for (int mt = 0; mt < 2; mt++) {
        const int gr0 = row0 + wm * 32 + mt * 16 + (l >> 2);
        const int gr1 = gr0 + 8;
        const float inv0 = (gr0 < NROWS) ? KV_SCALE_INV / g_norm[gr0] : 0.0f;
        const float inv1 = (gr1 < NROWS) ? KV_SCALE_INV / g_norm[gr1] : 0.0f;
#pragma unroll
        for (int nt = 0; nt < 8; nt++) {
            const int col = col0 + wn * 64 + nt * 8 + (l & 3) * 2;
            if (gr0 < NROWS)
                *(float2*)&out[gr0 * DIM + col] =
                    make_float2(c[mt][nt][0] * inv0, c[mt][nt][1] * inv0);
            if (gr1 < NROWS)
                *(float2*)&out[gr1 * DIM + col] =
                    make_float2(c[mt][nt][2] * inv1, c[mt][nt][3] * inv1);
        }
    }
}

// ---------------------------------------------------------------------------
extern "C" void kernel_launch(void* const* d_in, const int* in_sizes, int n_in,
                              void* d_out, int out_size) {
    const float* x  = (const float*)d_in[0];
    const float* Wq = (const float*)d_in[1];
    const float* bq = (const float*)d_in[2];
    const float* Wk = (const float*)d_in[3];
    const float* bk = (const float*)d_in[4];
    const float* Wv = (const float*)d_in[5];
    const float* bv = (const float*)d_in[6];
    float* out = (float*)d_out;

    cudaFuncSetAttribute(qkv_kernel, cudaFuncAttributeMaxDynamicSharedMemorySize, QKV_SMEM);
    cudaFuncSetAttribute(kvnorm_kernel, cudaFuncAttributeMaxDynamicSharedMemorySize, KV_SMEM);
    cudaFuncSetAttribute(out_kernel, cudaFuncAttributeMaxDynamicSharedMemorySize, OUT_SMEM);

    const int rowTiles = NPAD / 128;   // 782

    prep_kernel<<<12661, 256>>>(x, Wq, Wk, Wv);
    qkv_kernel<<<dim3(6, rowTiles), 256, QKV_SMEM>>>(bq, bk, bv);
    kvnorm_kernel<<<KV_BLOCKS + NORM_BLOCKS, 128, KV_SMEM>>>();
    kvh_kernel<<<DIM * DIM / 1024, 256>>>();
    out_kernel<<<dim3(2, rowTiles), 256, OUT_SMEM>>>(out);
}

// round 17
// speedup vs baseline: 1.0574x; 1.0574x over previous
#include <cuda_runtime.h>
#include <cuda_fp16.h>
#include <cstdint>

#define NROWS 100000
#define NPAD  100096          // 782 * 128
#define DIM 256
#define EPS 1e-6f
#define KV_SCALE_INV 256.0f   // KVh = KV / 256

#define SA 40                 // A-tile row stride (halves), 128 rows x 32 k
#define SB 136                // B/K/V-tile row stride (halves), 32 rows x 128 cols
#define ABYTES (128 * SA * 2)
#define BBYTES (32 * SB * 2)
#define STAGES 4              // qkv/out: 4 stages, ONE barrier/tile (R15 best)
#define KV_STAGES 3           // kv: 3 stages, two barriers (R10 best)

#define QKV_SMEM (STAGES * (ABYTES + BBYTES))      // 75776
#define OUT_SMEM (STAGES * (ABYTES + BBYTES))
#define KV_SMEM  (KV_STAGES * 2 * BBYTES)          // 52224

#define KV_NCHUNK 125
#define KV_TILES 25           // 25*32 = 800 rows/chunk; 125*800 = 100000 exactly

// Scratch (allocation-guard-safe __device__ globals)
__device__ __half g_xh[NPAD * DIM];      // x as fp16 (pad rows stay zero)
__device__ __half g_Q[NPAD * DIM];
__device__ __half g_K[NPAD * DIM];
__device__ __half g_V[NPAD * DIM];
__device__ __half g_Wh[3 * DIM * DIM];   // [z][k][n] fp16
__device__ float  g_KV[DIM * DIM];
__device__ __half g_KVh[DIM * DIM];      // KV / 256 as fp16, [d][e]
__device__ float  g_ksum[DIM];

// ---------------------------------------------------------------------------
// PTX helpers
// ---------------------------------------------------------------------------
__device__ __forceinline__ uint32_t smem_u32(const void* p) {
    uint32_t a;
    asm("{ .reg .u64 t; cvta.to.shared.u64 t, %1; cvt.u32.u64 %0, t; }" : "=r"(a) : "l"(p));
    return a;
}

__device__ __forceinline__ void cp16(uint32_t dst, const void* src) {
    asm volatile("cp.async.cg.shared.global [%0], [%1], 16;" :: "r"(dst), "l"(src));
}
#define CP_COMMIT() asm volatile("cp.async.commit_group;" ::: "memory")
#define CP_WAIT(n)  asm volatile("cp.async.wait_group %0;" :: "n"(n) : "memory")

#define LDSM_X4(r, addr) \
    asm volatile("ldmatrix.sync.aligned.m8n8.x4.shared.b16 {%0,%1,%2,%3}, [%4];" \
                 : "=r"((r)[0]), "=r"((r)[1]), "=r"((r)[2]), "=r"((r)[3]) : "r"(addr))
#define LDSM_X4T(r, addr) \
    asm volatile("ldmatrix.sync.aligned.m8n8.x4.trans.shared.b16 {%0,%1,%2,%3}, [%4];" \
                 : "=r"((r)[0]), "=r"((r)[1]), "=r"((r)[2]), "=r"((r)[3]) : "r"(addr))

#define LDS128(r0, r1, r2, r3, addr) \
    asm volatile("ld.shared.v4.u32 {%0,%1,%2,%3}, [%4];" \
                 : "=r"(r0), "=r"(r1), "=r"(r2), "=r"(r3) : "r"(addr))

__device__ __forceinline__ void mma_fp16(float c[4], const uint32_t a[4],
                                         uint32_t b0, uint32_t b1) {
    asm volatile(
        "mma.sync.aligned.m16n8k16.row.col.f32.f16.f16.f32 "
        "{%0,%1,%2,%3},{%4,%5,%6,%7},{%8,%9},{%0,%1,%2,%3};\n"
        : "+f"(c[0]), "+f"(c[1]), "+f"(c[2]), "+f"(c[3])
        : "r"(a[0]), "r"(a[1]), "r"(a[2]), "r"(a[3]), "r"(b0), "r"(b1));
}

__device__ __forceinline__ uint32_t pack_h2(float a, float b) {
    __half2 h = __floats2half2_rn(a, b);
    return *reinterpret_cast<uint32_t*>(&h);
}

// ---------------------------------------------------------------------------
// prep: x -> fp16, W -> fp16, AND zero KV/ksum accumulators (init fused)
// ---------------------------------------------------------------------------
__global__ void prep_kernel(const float* __restrict__ x,
                            const float* __restrict__ Wq,
                            const float* __restrict__ Wk,
                            const float* __restrict__ Wv) {
    const long id = (long)blockIdx.x * 256 + threadIdx.x;
    const long xgroups = (long)NROWS * DIM / 8;     // 3,200,000
    const long wgroups = 3 * DIM * DIM / 8;         // 24,576
    if (id < xgroups + wgroups) {
        const float* src;
        __half* dst;
        long off;
        if (id < xgroups) {
            src = x; dst = g_xh; off = id * 8;
        } else {
            const long wi = id - xgroups;
            const int z = (int)(wi >> 13);           // 8192 groups per matrix
            src = (z == 0) ? Wq : (z == 1) ? Wk : Wv;
            dst = g_Wh + z * DIM * DIM;
            off = (wi & 8191) * 8;
        }
        const float4 f0 = *(const float4*)&src[off];
        const float4 f1 = *(const float4*)&src[off + 4];
        uint4 u;
        u.x = pack_h2(f0.x, f0.y); u.y = pack_h2(f0.z, f0.w);
        u.z = pack_h2(f1.x, f1.y); u.w = pack_h2(f1.z, f1.w);
        *(uint4*)&dst[off] = u;
    } else {
        const long id3 = id - (xgroups + wgroups);
        if (id3 < DIM * DIM / 4) {                   // zero KV (float4)
            *(float4*)&g_KV[id3 * 4] = make_float4(0.f, 0.f, 0.f, 0.f);
            if (id3 < DIM / 4)                       // zero ksum
                *(float4*)&g_ksum[id3 * 4] = make_float4(0.f, 0.f, 0.f, 0.f);
        }
    }
}

// ---------------------------------------------------------------------------
// qkv: 256 thr, 128x128 tile, 4x2 warps of 32x64. ksum fused (z==1)
// grid (6, 782). 4-stage single-barrier pipeline.  (R15 best shape)
// ---------------------------------------------------------------------------
__global__ __launch_bounds__(256, 2) void qkv_kernel(
    const float* __restrict__ bq, const float* __restrict__ bk,
    const float* __restrict__ bv)
{
    extern __shared__ char dsm[];
    __shared__ float colsum[128];

    const int t = threadIdx.x;
    const int l = t & 31, w = t >> 5;
    const int wm = w >> 1, wn = w & 1;

    const int zy = blockIdx.x;
    const int z = zy >> 1;
    const int col0 = (zy & 1) * 128;
    const int row0 = blockIdx.y * 128;

    const __half* Wh = g_Wh + z * DIM * DIM;
    const float* bias = (z == 0) ? bq : (z == 1) ? bk : bv;
    __half* C = (z == 0) ? g_Q : (z == 1) ? g_K : g_V;
    const bool relu = (z < 2);

    if (t < 128) colsum[t] = 0.0f;

    const uint32_t as_base = smem_u32(dsm);
    const uint32_t bs_base = as_base + STAGES * ABYTES;
    const int aoff = (l & 15) * SA + (l >> 4) * 8;
    const int boff = ((l & 7) + ((l >> 3) & 1) * 8) * SB + (l >> 4) * 8;

    float c[2][8][4];
#pragma unroll
    for (int mt = 0; mt < 2; mt++)
#pragma unroll
        for (int nt = 0; nt < 8; nt++)
#pragma unroll
            for (int r = 0; r < 4; r++) c[mt][nt][r] = 0.0f;

    auto cp = [&](int kt) {
        const int s = kt % STAGES;
        const uint32_t da = as_base + s * ABYTES;
#pragma unroll
        for (int i = 0; i < 2; i++) {
            const int id = t + i * 256;
            const int row = id >> 2, cg = id & 3;
            cp16(da + (row * SA + cg * 8) * 2,
                 &g_xh[(row0 + row) * DIM + kt * 32 + cg * 8]);
        }
        const uint32_t db = bs_base + s * BBYTES;
#pragma unroll
        for (int i = 0; i < 2; i++) {
            const int id = t + i * 256;
            const int row = id >> 4, cg = id & 15;
            cp16(db + (row * SB + cg * 8) * 2,
                 &Wh[(kt * 32 + row) * DIM + col0 + cg * 8]);
        }
        CP_COMMIT();
    };
    auto compute = [&](int s) {
        const uint32_t ab = as_base + s * ABYTES;
        const uint32_t bb = bs_base + s * BBYTES;
#pragma unroll
        for (int ks = 0; ks < 2; ks++) {
            uint32_t a[2][4];
#pragma unroll
            for (int mt = 0; mt < 2; mt++)
                LDSM_X4(a[mt], ab + 2 * ((wm * 32 + mt * 16) * SA + ks * 16 + aoff));
            uint32_t b[4][4];
#pragma unroll
            for (int nt2 = 0; nt2 < 4; nt2++)
                LDSM_X4T(b[nt2], bb + 2 * (ks * 16 * SB + wn * 64 + nt2 * 16 + boff));
#pragma unroll
            for (int mt = 0; mt < 2; mt++)
#pragma unroll
                for (int nt = 0; nt < 8; nt++) {
                    const int nt2 = nt >> 1, i0 = (nt & 1) * 2;
                    mma_fp16(c[mt][nt], a[mt], b[nt2][i0], b[nt2][i0 + 1]);
                }
        }
    };

    cp(0); cp(1);
#pragma unroll 1
    for (int kt = 0; kt < 8; kt++) {
        if (kt + 2 < 8) cp(kt + 2);
        if (kt < 6) CP_WAIT(2); else if (kt == 6) CP_WAIT(1); else CP_WAIT(0);
        __syncthreads();
        compute(kt % STAGES);
    }

#pragma unroll
    for (int mt = 0; mt < 2; mt++) {
        const int gr0 = row0 + wm * 32 + mt * 16 + (l >> 2);
        const int gr1 = gr0 + 8;
#pragma unroll
        for (int nt = 0; nt < 8; nt++) {
            const int col = col0 + wn * 64 + nt * 8 + (l & 3) * 2;
            const float bb0 = bias[col], bb1 = bias[col + 1];
            float v0 = c[mt][nt][0] + bb0, v1 = c[mt][nt][1] + bb1;
            float v2 = c[mt][nt][2] + bb0, v3 = c[mt][nt][3] + bb1;
            if (relu) {
                v0 = fmaxf(v0, 0.f); v1 = fmaxf(v1, 0.f);
                v2 = fmaxf(v2, 0.f); v3 = fmaxf(v3, 0.f);
            }
            *(__half2*)&C[gr0 * DIM + col] = __floats2half2_rn(v0, v1);
            *(__half2*)&C[gr1 * DIM + col] = __floats2half2_rn(v2, v3);
            if (z == 1) {
                float s0 = (gr0 < NROWS ? v0 : 0.f) + (gr1 < NROWS ? v2 : 0.f);
                float s1 = (gr0 < NROWS ? v1 : 0.f) + (gr1 < NROWS ? v3 : 0.f);
                atomicAdd(&colsum[col - col0], s0);
                atomicAdd(&colsum[col - col0 + 1], s1);
            }
        }
    }
    if (z == 1) {
        __syncthreads();
        if (t < 128) atomicAdd(&g_ksum[col0 + t], colsum[t]);
    }
}

// ---------------------------------------------------------------------------
// kv: 128 thr, 2x2 warps of 64x64, 3-stage two-barrier (R10 measured best)
// grid (4, 125): x fastest -> chunk K/V tiles reused via L2
// ---------------------------------------------------------------------------
__global__ __launch_bounds__(128, 2) void kv_kernel() {
    extern __shared__ char dsm[];

    const int t = threadIdx.x;
    const int l = t & 31, w = t >> 5;
    const int wm = w >> 1, wn = w & 1;

    const int d0 = (blockIdx.x & 1) * 128;
    const int e0 = (blockIdx.x >> 1) * 128;
    const int n0 = blockIdx.y * (KV_TILES * 32);

    const uint32_t kb_base = smem_u32(dsm);
    const uint32_t vb_base = kb_base + KV_STAGES * BBYTES;
    const int kaoff = ((l & 7) + (l >> 4) * 8) * SB + ((l >> 3) & 1) * 8;
    const int boff  = ((l & 7) + ((l >> 3) & 1) * 8) * SB + (l >> 4) * 8;

    float c[4][8][4];
#pragma unroll
    for (int mt = 0; mt < 4; mt++)
#pragma unroll
        for (int nt = 0; nt < 8; nt++)
#pragma unroll
            for (int r = 0; r < 4; r++) c[mt][nt][r] = 0.0f;

    auto cp = [&](int kt) {
        const int s = kt % KV_STAGES;
        const uint32_t kd = kb_base + s * BBYTES;
        const uint32_t vd = vb_base + s * BBYTES;
        const int gn0 = n0 + kt * 32;
#pragma unroll
        for (int i = 0; i < 4; i++) {
            const int id = t + i * 128;
            const int row = id >> 4, cg = id & 15;
            cp16(kd + (row * SB + cg * 8) * 2, &g_K[(gn0 + row) * DIM + d0 + cg * 8]);
            cp16(vd + (row * SB + cg * 8) * 2, &g_V[(gn0 + row) * DIM + e0 + cg * 8]);
        }
        CP_COMMIT();
    };
    auto compute = [&](int s) {
        const uint32_t kb = kb_base + s * BBYTES;
        const uint32_t vb = vb_base + s * BBYTES;
#pragma unroll
        for (int ks = 0; ks < 2; ks++) {
            uint32_t a[4][4];
#pragma unroll
            for (int mt = 0; mt < 4; mt++)
                LDSM_X4T(a[mt], kb + 2 * (ks * 16 * SB + wm * 64 + mt * 16 + kaoff));
            uint32_t b[4][4];
#pragma unroll
            for (int nt2 = 0; nt2 < 4; nt2++)
                LDSM_X4T(b[nt2], vb + 2 * (ks * 16 * SB + wn * 64 + nt2 * 16 + boff));
#pragma unroll
            for (int mt = 0; mt < 4; mt++)
#pragma unroll
                for (int nt = 0; nt < 8; nt++) {
                    const int nt2 = nt >> 1, i0 = (nt & 1) * 2;
                    mma_fp16(c[mt][nt], a[mt], b[nt2][i0], b[nt2][i0 + 1]);
                }
        }
    };

    cp(0); cp(1);
#pragma unroll 1
    for (int kt = 0; kt < KV_TILES; kt++) {
        if (kt + 2 < KV_TILES) cp(kt + 2);
        if (kt < KV_TILES - 2) CP_WAIT(2);
        else if (kt == KV_TILES - 2) CP_WAIT(1);
        else CP_WAIT(0);
        __syncthreads();
        compute(kt % KV_STAGES);
        __syncthreads();
    }

#pragma unroll
    for (int mt = 0; mt < 4; mt++) {
        const int dr0 = d0 + wm * 64 + mt * 16 + (l >> 2);
#pragma unroll
        for (int nt = 0; nt < 8; nt++) {
            const int ec = e0 + wn * 64 + nt * 8 + (l & 3) * 2;
            atomicAdd(&g_KV[dr0 * DIM + ec],           c[mt][nt][0]);
            atomicAdd(&g_KV[dr0 * DIM + ec + 1],       c[mt][nt][1]);
            atomicAdd(&g_KV[(dr0 + 8) * DIM + ec],     c[mt][nt][2]);
            atomicAdd(&g_KV[(dr0 + 8) * DIM + ec + 1], c[mt][nt][3]);
        }
    }
}

// ---------------------------------------------------------------------------
// kvh: KVh = fp16(KV / 256)
// ---------------------------------------------------------------------------
__global__ void kvh_kernel() {
    const int i = (blockIdx.x * 256 + threadIdx.x) * 4;
    const float4 f = *(const float4*)&g_KV[i];
    const float s = 1.0f / KV_SCALE_INV;
    uint2 u;
    u.x = pack_h2(f.x * s, f.y * s);
    u.y = pack_h2(f.z * s, f.w * s);
    *(uint2*)&g_KVh[i] = u;
}

// ---------------------------------------------------------------------------
// out (+norm fused): out = (Q @ KVh) * 256 / (Q.ksum + EPS)
// The normalizer is accumulated from the SAME A-smem Q tiles the GEMM streams.
// grid (2, 782), 4-stage single-barrier pipeline.
// ---------------------------------------------------------------------------
__global__ __launch_bounds__(256, 2) void out_kernel(float* __restrict__ out) {
    extern __shared__ char dsm[];
    __shared__ float ksm[DIM];    // ksum
    __shared__ float nsm[128];    // per-row normalizer

    const int t = threadIdx.x;
    const int l = t & 31, w = t >> 5;
    const int wm = w >> 1, wn = w & 1;

    const int col0 = blockIdx.x * 128;
    const int row0 = blockIdx.y * 128;

    ksm[t] = g_ksum[t];           // 256 threads load all 256 ksum values

    const uint32_t as_base = smem_u32(dsm);
    const uint32_t bs_base = as_base + STAGES * ABYTES;
    const int aoff = (l & 15) * SA + (l >> 4) * 8;
    const int boff = ((l & 7) + ((l >> 3) & 1) * 8) * SB + (l >> 4) * 8;

    // norm accumulation mapping: thread t handles row (t>>1), k-half (t&1)
    const int nrow = t >> 1;
    const int nhalf = t & 1;

    float c[2][8][4];
#pragma unroll
    for (int mt = 0; mt < 2; mt++)
#pragma unroll
        for (int nt = 0; nt < 8; nt++)
#pragma unroll
            for (int r = 0; r < 4; r++) c[mt][nt][r] = 0.0f;

    float nacc = 0.0f;

    auto cp = [&](int kt) {
        const int s = kt % STAGES;
        const uint32_t da = as_base + s * ABYTES;
#pragma unroll
        for (int i = 0; i < 2; i++) {
            const int id = t + i * 256;
            const int row = id >> 2, cg = id & 3;
            cp16(da + (row * SA + cg * 8) * 2,
                 &g_Q[(row0 + row) * DIM + kt * 32 + cg * 8]);
        }
        const uint32_t db = bs_base + s * BBYTES;
#pragma unroll
        for (int i = 0; i < 2; i++) {
            const int id = t + i * 256;
            const int row = id >> 4, cg = id & 15;
            cp16(db + (row * SB + cg * 8) * 2,
                 &g_KVh[(kt * 32 + row) * DIM + col0 + cg * 8]);
        }
        CP_COMMIT();
    };
    auto compute = [&](int s) {
        const uint32_t ab = as_base + s * ABYTES;
        const uint32_t bb = bs_base + s * BBYTES;
#pragma unroll
        for (int ks = 0; ks < 2; ks++) {
            uint32_t a[2][4];
#pragma unroll
            for (int mt = 0; mt < 2; mt++)
                LDSM_X4(a[mt], ab + 2 * ((wm * 32 + mt * 16) * SA + ks * 16 + aoff));
            uint32_t b[4][4];
#pragma unroll
            for (int nt2 = 0; nt2 < 4; nt2++)
                LDSM_X4T(b[nt2], bb + 2 * (ks * 16 * SB + wn * 64 + nt2 * 16 + boff));
#pragma unroll
            for (int mt = 0; mt < 2; mt++)
#pragma unroll
                for (int nt = 0; nt < 8; nt++) {
                    const int nt2 = nt >> 1, i0 = (nt & 1) * 2;
                    mma_fp16(c[mt][nt], a[mt], b[nt2][i0], b[nt2][i0 + 1]);
                }
        }
    };
    auto norm_acc = [&](int kt) {
        // read Q[nrow][kt*32 + nhalf*16 .. +16] from the A tile just consumed
        const uint32_t ab = as_base + (kt % STAGES) * ABYTES;
        const uint32_t base = ab + 2 * (nrow * SA + nhalf * 16);
        uint32_t d[8];
        LDS128(d[0], d[1], d[2], d[3], base);
        LDS128(d[4], d[5], d[6], d[7], base + 16);
        const __half2* h = (const __half2*)d;
        const float* kp = &ksm[kt * 32 + nhalf * 16];
#pragma unroll
        for (int j = 0; j < 8; j++) {
            const float2 f = __half22float2(h[j]);
            nacc += f.x * kp[j * 2] + f.y * kp[j * 2 + 1];
        }
    };

    cp(0); cp(1);
#pragma unroll 1
    for (int kt = 0; kt < 8; kt++) {
        if (kt + 2 < 8) cp(kt + 2);
        if (kt < 6) CP_WAIT(2); else if (kt == 6) CP_WAIT(1); else CP_WAIT(0);
        __syncthreads();
        compute(kt % STAGES);
        norm_acc(kt);
    }

    // publish per-row normalizer: threads t and t^1 hold the two k-halves
    nacc += __shfl_xor_sync(0xffffffffu, nacc, 1);
    if (!(t & 1)) nsm[nrow] = nacc + EPS;
    __syncthreads();

#pragma unroll
    for (int mt = 0; mt < 2; mt++) {
        const int lr0 = wm * 32 + mt * 16 + (l >> 2);
        const int gr0 = row0 + lr0;
        const int gr1 = gr0 + 8;
        const float inv0 = KV_SCALE_INV / nsm[lr0];
        const float inv1 = KV_SCALE_INV / nsm[lr0 + 8];
#pragma unroll
        for (int nt = 0; nt < 8; nt++) {
            const int col = col0 + wn * 64 + nt * 8 + (l & 3) * 2;
            if (gr0 < NROWS)
                *(float2*)&out[gr0 * DIM + col] =
                    make_float2(c[mt][nt][0] * inv0, c[mt][nt][1] * inv0);
            if (gr1 < NROWS)
                *(float2*)&out[gr1 * DIM + col] =
                    make_float2(c[mt][nt][2] * inv1, c[mt][nt][3] * inv1);
        }
    }
}

// ---------------------------------------------------------------------------
extern "C" void kernel_launch(void* const* d_in, const int* in_sizes, int n_in,
                              void* d_out, int out_size) {
    const float* x  = (const float*)d_in[0];
    const float* Wq = (const float*)d_in[1];
    const float* bq = (const float*)d_in[2];
    const float* Wk = (const float*)d_in[3];
    const float* bk = (const float*)d_in[4];
    const float* Wv = (const float*)d_in[5];
    const float* bv = (const float*)d_in[6];
    float* out = (float*)d_out;

    cudaFuncSetAttribute(qkv_kernel, cudaFuncAttributeMaxDynamicSharedMemorySize, QKV_SMEM);
    cudaFuncSetAttribute(kv_kernel,  cudaFuncAttributeMaxDynamicSharedMemorySize, KV_SMEM);
    cudaFuncSetAttribute(out_kernel, cudaFuncAttributeMaxDynamicSharedMemorySize, OUT_SMEM);

    const int rowTiles = NPAD / 128;   // 782

    prep_kernel<<<12661, 256>>>(x, Wq, Wk, Wv);
    qkv_kernel<<<dim3(6, rowTiles), 256, QKV_SMEM>>>(bq, bk, bv);
    kv_kernel<<<dim3(4, KV_NCHUNK), 128, KV_SMEM>>>();
    kvh_kernel<<<DIM * DIM / 1024, 256>>>();
    out_kernel<<<dim3(2, rowTiles), 256, OUT_SMEM>>>(out);
}